// round 1
// baseline (speedup 1.0000x reference)
#include <cuda_runtime.h>
#include <cstddef>

// Problem constants
#define NN    16
#define DIM   32
#define FEAT  192
#define KTOT  (DIM*FEAT)      // 6144
#define YSZ   (NN*DIM*FEAT)   // 98304

// Einsum tiling
#define KSPLIT 4
#define KCTA   (KTOT/KSPLIT)  // 1536
#define KWARP  (KCTA/4)       // 384
#define NSTAGE (KWARP/32)     // 12

// Scratch (no allocations allowed -> device globals)
__device__ float g_ybuf[YSZ];
__device__ float g_h1[YSZ];
__device__ float g_h2[YSZ];

// ---------------------------------------------------------------------------
// Fused weighted einsum:
//   Y[n, m, c] += sum_k  Htilde[n,k,c] * W[k, c, m]
//   Htilde = H0[n,k]*A0[k%192, c]  (+ H1[n,k]*A1[k%192, c] if TWO_H)
// W viewed as [KTOT][FEAT][DIM] (this is exactly s2t's / t2s's memory layout).
// One warp handles one (c, k-chunk); lane = m (=d). Inner loop uses packed
// fma.rn.f32x2 over n-pairs.
// ---------------------------------------------------------------------------
template<bool TWO_H>
__global__ void __launch_bounds__(128, 6)
einsum_kernel(const float* __restrict__ W,
              const float* __restrict__ H0, const float* __restrict__ A0,
              const float* __restrict__ H1, const float* __restrict__ A1,
              float* __restrict__ Y)
{
    const int c    = blockIdx.y;     // 0..191
    const int ks   = blockIdx.x;     // 0..KSPLIT-1
    const int tid  = threadIdx.x;
    const int w    = tid >> 5;
    const int lane = tid & 31;

    __shared__ __align__(16) float2 sh_h[4][32][8];  // [warp][kk][n-pair] = 8KB
    __shared__ float sh_a0[FEAT];
    __shared__ float sh_a1[FEAT];

    // Stage the A column(s) for this c.
    for (int i = tid; i < FEAT; i += 128) {
        sh_a0[i] = A0[i * FEAT + c];
        if (TWO_H) sh_a1[i] = A1[i * FEAT + c];
    }
    __syncthreads();

    unsigned long long acc[8];
#pragma unroll
    for (int p = 0; p < 8; ++p) acc[p] = 0ull;   // packed {0.f, 0.f}

    const int kwbase = ks * KCTA + w * KWARP;
    // W element address: ((k*FEAT)+c)*DIM + lane ; per-k stride = FEAT*DIM = KTOT
    const float* Wp0 = W + ((size_t)kwbase * FEAT + c) * DIM + lane;

    for (int s = 0; s < NSTAGE; ++s) {
        const int kb = kwbase + s * 32;

        // ---- stage h-tilde for 32 k's: lane handles k = kb+lane, all 16 n ----
        {
            const int k = kb + lane;
            // kb is a multiple of 32 and 32 | 192 -> no wrap needed
            const int f = (kb % FEAT) + lane;
            const float a0 = sh_a0[f];
            const float* hp0 = H0 + k;
            float a1 = 0.f; const float* hp1 = nullptr;
            if (TWO_H) { a1 = sh_a1[f]; hp1 = H1 + k; }
#pragma unroll
            for (int p = 0; p < 8; ++p) {
                float x0 = hp0[(2 * p)     * KTOT] * a0;
                float x1 = hp0[(2 * p + 1) * KTOT] * a0;
                if (TWO_H) {
                    x0 = fmaf(hp1[(2 * p)     * KTOT], a1, x0);
                    x1 = fmaf(hp1[(2 * p + 1) * KTOT], a1, x1);
                }
                sh_h[w][lane][p] = make_float2(x0, x1);
            }
        }
        __syncwarp();

        // ---- compute: 32 k's, 8 packed FMAs each ----
        const float* Wp = Wp0 + (size_t)s * 32 * KTOT;
#pragma unroll
        for (int kk = 0; kk < 32; ++kk) {
            const float wv = Wp[(size_t)kk * KTOT];   // coalesced 128B/warp
            unsigned long long wd;
            asm("mov.b64 %0, {%1, %1};" : "=l"(wd) : "f"(wv));
            const ulonglong2* hr =
                reinterpret_cast<const ulonglong2*>(&sh_h[w][kk][0]);
#pragma unroll
            for (int q = 0; q < 4; ++q) {
                ulonglong2 hh = hr[q];   // LDS.128: two packed n-pairs
                asm("fma.rn.f32x2 %0, %1, %2, %0;"
                    : "+l"(acc[2 * q])     : "l"(hh.x), "l"(wd));
                asm("fma.rn.f32x2 %0, %1, %2, %0;"
                    : "+l"(acc[2 * q + 1]) : "l"(hh.y), "l"(wd));
            }
        }
        __syncwarp();
    }

    // ---- reduce the 4 warps' partial tiles, then one atomicAdd per output ----
    __syncthreads();
    float* sred = reinterpret_cast<float*>(sh_h);    // 2048 floats, reused
#pragma unroll
    for (int p = 0; p < 8; ++p) {
        float lo, hi;
        asm("mov.b64 {%0, %1}, %2;" : "=f"(lo), "=f"(hi) : "l"(acc[p]));
        sred[(w * 16 + 2 * p)     * 32 + lane] = lo;
        sred[(w * 16 + 2 * p + 1) * 32 + lane] = hi;
    }
    __syncthreads();
    for (int idx = tid; idx < 512; idx += 128) {
        const float sum = sred[idx] + sred[512 + idx] +
                          sred[1024 + idx] + sred[1536 + idx];
        const int n = idx >> 5;
        const int d = idx & 31;
        atomicAdd(&Y[(n * DIM + d) * FEAT + c], sum);
    }
}

// ---------------------------------------------------------------------------
// Plain transition matmul:  Y[row, c] = sum_f H[row, f] * M[f, c]
// (row = flattened n*32+dim, 512 rows). Overwrites Y (initializes the layer
// accumulation buffer), einsum kernel then atomicAdds on top.
// ---------------------------------------------------------------------------
__global__ void matmul_kernel(const float* __restrict__ H,
                              const float* __restrict__ M,
                              float* __restrict__ Y)
{
    __shared__ float sh[FEAT];
    const int row = blockIdx.x;
    const int t   = threadIdx.x;
    sh[t] = H[row * FEAT + t];
    __syncthreads();
    float s0 = 0.f, s1 = 0.f, s2 = 0.f, s3 = 0.f;
#pragma unroll 8
    for (int f = 0; f < FEAT; f += 4) {
        s0 = fmaf(sh[f    ], M[(f    ) * FEAT + t], s0);
        s1 = fmaf(sh[f + 1], M[(f + 1) * FEAT + t], s1);
        s2 = fmaf(sh[f + 2], M[(f + 2) * FEAT + t], s2);
        s3 = fmaf(sh[f + 3], M[(f + 3) * FEAT + t], s3);
    }
    Y[row * FEAT + t] = (s0 + s1) + (s2 + s3);
}

// ---------------------------------------------------------------------------
// LayerNorm over last two dims (6144 elems per n), eps=1e-5, no affine.
// NOTE: LN is invariant to positive scaling, so the reference's mean-over-
// terms division is skipped entirely.
// ---------------------------------------------------------------------------
__global__ void ln_kernel(const float* __restrict__ Y, float* __restrict__ O)
{
    const int n = blockIdx.x;
    const int t = threadIdx.x;
    const float* y = Y + (size_t)n * KTOT;

    float s = 0.f, q = 0.f;
    for (int i = t; i < KTOT; i += 384) {
        const float v = y[i];
        s += v;
        q = fmaf(v, v, q);
    }
#pragma unroll
    for (int o = 16; o > 0; o >>= 1) {
        s += __shfl_xor_sync(0xffffffffu, s, o);
        q += __shfl_xor_sync(0xffffffffu, q, o);
    }
    __shared__ float ss[12], qs[12];
    __shared__ float mean_b, rstd_b;
    const int wid = t >> 5, ln = t & 31;
    if (ln == 0) { ss[wid] = s; qs[wid] = q; }
    __syncthreads();
    if (t == 0) {
        float S = 0.f, Q = 0.f;
#pragma unroll
        for (int i = 0; i < 12; ++i) { S += ss[i]; Q += qs[i]; }
        const float mean = S * (1.0f / KTOT);
        const float var  = Q * (1.0f / KTOT) - mean * mean;
        mean_b = mean;
        rstd_b = rsqrtf(var + 1e-5f);
    }
    __syncthreads();
    const float mean = mean_b, rstd = rstd_b;
    for (int i = t; i < KTOT; i += 384)
        O[(size_t)n * KTOT + i] = (y[i] - mean) * rstd;
}

// ---------------------------------------------------------------------------
extern "C" void kernel_launch(void* const* d_in, const int* in_sizes, int n_in,
                              void* d_out, int out_size)
{
    const float* x   = (const float*)d_in[0];
    const float* s2t = (const float*)d_in[1];
    const float* t2s = (const float*)d_in[2];
    const float* s0  = (const float*)d_in[3];
    const float* s1  = (const float*)d_in[4];
    // d_in[5] = s2 : unused by the 4-layer schedule
    const float* t0  = (const float*)d_in[6];
    const float* t1  = (const float*)d_in[7];
    const float* t2  = (const float*)d_in[8];
    float* out = (float*)d_out;

    float *ybuf, *h1, *h2;
    cudaGetSymbolAddress((void**)&ybuf, g_ybuf);
    cudaGetSymbolAddress((void**)&h1,   g_h1);
    cudaGetSymbolAddress((void**)&h2,   g_h2);

    const dim3 eg(KSPLIT, FEAT);

    // Layer 1: y1 = einsum(h0=x, s2t, t0) -> LN -> h1
    cudaMemsetAsync(ybuf, 0, YSZ * sizeof(float));
    einsum_kernel<false><<<eg, 128>>>(s2t, x, t0, nullptr, nullptr, ybuf);
    ln_kernel<<<NN, 384>>>(ybuf, h1);

    // Layer 2: y2 = x@s1 + einsum(h1, t2s, s0) -> LN -> h2
    matmul_kernel<<<NN * DIM, FEAT>>>(x, s1, ybuf);
    einsum_kernel<false><<<eg, 128>>>(t2s, h1, s0, nullptr, nullptr, ybuf);
    ln_kernel<<<NN, 384>>>(ybuf, h2);

    // Layer 3: y3 = h1@t1 + einsum(x, s2t, t2) + einsum(h2, s2t, t0)
    //          (two s2t einsums fused into one W pass) -> LN -> out
    matmul_kernel<<<NN * DIM, FEAT>>>(h1, t1, ybuf);
    einsum_kernel<true><<<eg, 128>>>(s2t, x, t2, h2, t0, ybuf);
    ln_kernel<<<NN, 384>>>(ybuf, out);
}